// round 14
// baseline (speedup 1.0000x reference)
#include <cuda_runtime.h>
#include <cuda_bf16.h>
#include <cstdint>
#include <cstddef>

// ---------------------------------------------------------------------------
// Hyena operator: B=2, L=4096, D=1024, ORDER=2, OD=3072
// Round 14: FFT boundary-pass fusion (load+r2, inv-r2+gate+fwd-r2, inv-r2+out)
// -> 21 smem passes/CTA instead of 25. Rest as R13.
// ---------------------------------------------------------------------------

#define LSEQ 4096
#define NF   8192
#define DDIM 1024
#define ODIM 3072
#define BSZ  2
#define NPAIR 512
#define NK    4100
#define FFT_THREADS 256
#define FFT_ZP_IT (4096 / FFT_THREADS)
#define FFT_R8_IT (1024 / FFT_THREADS)
#define PADI(i) ((i) + ((i) >> 5))
#define SM_HALF 8448
#define FFT_SMEM (2 * SM_HALF * 4)

// Scratch (device .bss — allocation-free)
__device__ float  g_res[(size_t)BSZ * ODIM * LSEQ];
__device__ float  g_h  [(size_t)2   * DDIM * LSEQ];
__device__ float  g_sact[(size_t)LSEQ * 64];
__device__ float2 g_A  [(size_t)2 * NPAIR * NK];
__device__ float2 g_B  [(size_t)2 * NPAIR * NK];
__device__ float2 g_tw [NF];
// packed bf16 hi/lo operands (uint32 = 2 bf16)
__device__ uint32_t g_wh[(size_t)ODIM * DDIM / 2];
__device__ uint32_t g_wl[(size_t)ODIM * DDIM / 2];
__device__ uint32_t g_uh[(size_t)BSZ * LSEQ * DDIM / 2];
__device__ uint32_t g_ul[(size_t)BSZ * LSEQ * DDIM / 2];
__device__ uint32_t g_oh[(size_t)DDIM * DDIM / 2];
__device__ uint32_t g_ol[(size_t)DDIM * DDIM / 2];
__device__ uint32_t g_vh[(size_t)BSZ * DDIM * LSEQ / 2];
__device__ uint32_t g_vl[(size_t)BSZ * DDIM * LSEQ / 2];

// ---------------------------------------------------------------------------
__device__ __forceinline__ uint32_t smem_u32(const void* p) {
    uint32_t a;
    asm("{ .reg .u64 t; cvta.to.shared.u64 t, %1; cvt.u32.u64 %0, t; }" : "=r"(a) : "l"(p));
    return a;
}

#define LDSM_X4(r0, r1, r2, r3, addr) \
    asm volatile("ldmatrix.sync.aligned.m8n8.x4.shared.b16 {%0,%1,%2,%3}, [%4];" \
                 : "=r"(r0), "=r"(r1), "=r"(r2), "=r"(r3) : "r"(addr))
#define LDSM_X4_T(r0, r1, r2, r3, addr) \
    asm volatile("ldmatrix.sync.aligned.m8n8.x4.trans.shared.b16 {%0,%1,%2,%3}, [%4];" \
                 : "=r"(r0), "=r"(r1), "=r"(r2), "=r"(r3) : "r"(addr))
#define LDSM_X2(r0, r1, addr) \
    asm volatile("ldmatrix.sync.aligned.m8n8.x2.shared.b16 {%0,%1}, [%2];" \
                 : "=r"(r0), "=r"(r1) : "r"(addr))
#define CP_ASYNC16(dst, src) \
    asm volatile("cp.async.cg.shared.global [%0], [%1], 16;" :: "r"(dst), "l"(src))
#define CP_COMMIT() asm volatile("cp.async.commit_group;" ::: "memory")
#define CP_WAIT1()  asm volatile("cp.async.wait_group 1;" ::: "memory")

__device__ __forceinline__ void mma_bf16(float* c, const uint32_t* a, const uint32_t* b) {
    asm volatile(
        "mma.sync.aligned.m16n8k16.row.col.f32.bf16.bf16.f32 "
        "{%0,%1,%2,%3}, {%4,%5,%6,%7}, {%8,%9}, {%0,%1,%2,%3};"
        : "+f"(c[0]), "+f"(c[1]), "+f"(c[2]), "+f"(c[3])
        : "r"(a[0]), "r"(a[1]), "r"(a[2]), "r"(a[3]), "r"(b[0]), "r"(b[1]));
}

__device__ __forceinline__ uint32_t pack_hi(float x, float y) {
    __nv_bfloat16 hx = __float2bfloat16(x);
    __nv_bfloat16 hy = __float2bfloat16(y);
    return (uint32_t)__bfloat16_as_ushort(hx) | ((uint32_t)__bfloat16_as_ushort(hy) << 16);
}
__device__ __forceinline__ uint32_t pack_lo(float x, float y) {
    __nv_bfloat16 hx = __float2bfloat16(x);
    __nv_bfloat16 hy = __float2bfloat16(y);
    __nv_bfloat16 lx = __float2bfloat16(x - __bfloat162float(hx));
    __nv_bfloat16 ly = __float2bfloat16(y - __bfloat162float(hy));
    return (uint32_t)__bfloat16_as_ushort(lx) | ((uint32_t)__bfloat16_as_ushort(ly) << 16);
}

// mixed-radix [2,8,8,8,8] frequency -> slot map
__device__ __forceinline__ int freq_to_slot(int k) {
    return (k & 1) * 4096 + ((k >> 1) & 7) * 512 + ((k >> 4) & 7) * 64
         + ((k >> 7) & 7) * 8 + ((k >> 10) & 7);
}

// ---------------------------------------------------------------------------
// prep_kernel: sact + 3x cvt_split + twiddles, grid-partitioned.
#define PREP_SACT  1024
#define PREP_WIN   6144
#define PREP_U     16384
#define PREP_WOUT  2048
#define PREP_INIT  32
#define PREP_GRID  (PREP_SACT + PREP_WIN + PREP_U + PREP_WOUT + PREP_INIT)

__global__ __launch_bounds__(256) void prep_kernel(
    const float* __restrict__ w_in, const float* __restrict__ u,
    const float* __restrict__ w_out,
    const float* __restrict__ w1, const float* __restrict__ b1)
{
    const int bid = blockIdx.x;
    const int tid = threadIdx.x;
    if (bid < PREP_SACT) {
        int idx = bid * 256 + tid;
        int l = idx >> 6;
        int un = idx & 63;
        float t = (float)l * (1.0f / (float)(LSEQ - 1));
        float z = b1[un];
        #pragma unroll
        for (int j = 0; j < 33; j++) z += sinf(t * (float)j * 10.0f) * w1[un * 33 + j];
        g_sact[idx] = sinf(10.0f * z);
    } else if (bid < PREP_SACT + PREP_WIN) {
        int i = (bid - PREP_SACT) * 256 + tid;
        float2 v = ((const float2*)w_in)[i];
        g_wh[i] = pack_hi(v.x, v.y);
        g_wl[i] = pack_lo(v.x, v.y);
    } else if (bid < PREP_SACT + PREP_WIN + PREP_U) {
        int i = (bid - PREP_SACT - PREP_WIN) * 256 + tid;
        float2 v = ((const float2*)u)[i];
        g_uh[i] = pack_hi(v.x, v.y);
        g_ul[i] = pack_lo(v.x, v.y);
    } else if (bid < PREP_SACT + PREP_WIN + PREP_U + PREP_WOUT) {
        int i = (bid - PREP_SACT - PREP_WIN - PREP_U) * 256 + tid;
        float2 v = ((const float2*)w_out)[i];
        g_oh[i] = pack_hi(v.x, v.y);
        g_ol[i] = pack_lo(v.x, v.y);
    } else {
        int i = (bid - PREP_SACT - PREP_WIN - PREP_U - PREP_WOUT) * 256 + tid;
        double ang = -2.0 * 3.141592653589793238462643 * (double)i / (double)NF;
        g_tw[i] = make_float2((float)cos(ang), (float)sin(ang));
    }
}

// ---------------------------------------------------------------------------
// filter_gemm: g_h[o][l] (standalone launch)
__global__ __launch_bounds__(256) void filter_gemm(
    const float* __restrict__ w2, const float* __restrict__ b2,
    const float* __restrict__ fb, const float* __restrict__ fd)
{
    extern __shared__ float fsm[];
    float (*As)[128] = (float(*)[128])fsm;
    float (*Bs)[128] = (float(*)[128])(fsm + 64 * 128);
    const int l0 = (blockIdx.x & 31) * 128;
    const int o0 = (blockIdx.x >> 5) * 128;
    const int tid = threadIdx.x;
    const int tm = tid >> 4;
    const int tn = tid & 15;
    const int lrow = tid >> 1;
    const int lk   = (tid & 1) * 32;

    #pragma unroll
    for (int f = 0; f < 8; f++) {
        float4 a = *(const float4*)&w2[(size_t)(o0 + lrow) * 64 + lk + f * 4];
        As[lk + f * 4 + 0][lrow] = a.x; As[lk + f * 4 + 1][lrow] = a.y;
        As[lk + f * 4 + 2][lrow] = a.z; As[lk + f * 4 + 3][lrow] = a.w;
        float4 s = *(const float4*)&g_sact[(size_t)(l0 + lrow) * 64 + lk + f * 4];
        Bs[lk + f * 4 + 0][lrow] = s.x; Bs[lk + f * 4 + 1][lrow] = s.y;
        Bs[lk + f * 4 + 2][lrow] = s.z; Bs[lk + f * 4 + 3][lrow] = s.w;
    }
    __syncthreads();

    float acc[8][8];
    #pragma unroll
    for (int i = 0; i < 8; i++)
        #pragma unroll
        for (int j = 0; j < 8; j++) acc[i][j] = 0.0f;

    #pragma unroll
    for (int k = 0; k < 64; k++) {
        float4 ra0 = *(const float4*)&As[k][tm * 8];
        float4 ra1 = *(const float4*)&As[k][tm * 8 + 4];
        float4 rb0 = *(const float4*)&Bs[k][tn * 8];
        float4 rb1 = *(const float4*)&Bs[k][tn * 8 + 4];
        float ra[8] = {ra0.x, ra0.y, ra0.z, ra0.w, ra1.x, ra1.y, ra1.z, ra1.w};
        float rb[8] = {rb0.x, rb0.y, rb0.z, rb0.w, rb1.x, rb1.y, rb1.z, rb1.w};
        #pragma unroll
        for (int i = 0; i < 8; i++)
            #pragma unroll
            for (int j = 0; j < 8; j++) acc[i][j] += ra[i] * rb[j];
    }

    #pragma unroll
    for (int i = 0; i < 8; i++) {
        int o = o0 + tm * 8 + i;
        float ed  = expf(fd[o]);
        float bb  = b2[o];
        float fbo = fb[o];
        float v[8];
        #pragma unroll
        for (int j = 0; j < 8; j++) {
            int l = l0 + tn * 8 + j;
            float t = (float)l * (1.0f / (float)(LSEQ - 1));
            v[j] = ((acc[i][j] + bb) * expf(-ed * t) + fbo) * (1.0f / (float)LSEQ);
        }
        *(float4*)&g_h[(size_t)o * LSEQ + l0 + tn * 8]     = make_float4(v[0], v[1], v[2], v[3]);
        *(float4*)&g_h[(size_t)o * LSEQ + l0 + tn * 8 + 4] = make_float4(v[4], v[5], v[6], v[7]);
    }
}

// ---------------------------------------------------------------------------
// FFT radix-8 cores (no boundary radix-2 stages; those are fused by callers).
#define FFT_C 0.70710678118654752f

__device__ __forceinline__ void fft_fwd_r8(float* __restrict__ SR, float* __restrict__ SI) {
    #pragma unroll
    for (int s = 0; s < 4; s++) {
        const int lm  = 9 - 3 * s;
        const int m   = 1 << lm;
        const int str = 1024 >> lm;
        #pragma unroll
        for (int jj = 0; jj < FFT_R8_IT; jj++) {
            int t = threadIdx.x + jj * FFT_THREADS;
            int q = t & (m - 1);
            int base = ((t >> lm) << (lm + 3)) | q;
            int p0 = PADI(base), p1 = PADI(base + m), p2 = PADI(base + 2 * m),
                p3 = PADI(base + 3 * m), p4 = PADI(base + 4 * m), p5 = PADI(base + 5 * m),
                p6 = PADI(base + 6 * m), p7 = PADI(base + 7 * m);
            float x0r = SR[p0], x0i = SI[p0];
            float x1r = SR[p1], x1i = SI[p1];
            float x2r = SR[p2], x2i = SI[p2];
            float x3r = SR[p3], x3i = SI[p3];
            float x4r = SR[p4], x4i = SI[p4];
            float x5r = SR[p5], x5i = SI[p5];
            float x6r = SR[p6], x6i = SI[p6];
            float x7r = SR[p7], x7i = SI[p7];
            float a0r = x0r + x4r, a0i = x0i + x4i;
            float a1r = x1r + x5r, a1i = x1i + x5i;
            float a2r = x2r + x6r, a2i = x2i + x6i;
            float a3r = x3r + x7r, a3i = x3i + x7i;
            float b0r = x0r - x4r, b0i = x0i - x4i;
            float b1r = x1r - x5r, b1i = x1i - x5i;
            float b2r = x2r - x6r, b2i = x2i - x6i;
            float b3r = x3r - x7r, b3i = x3i - x7i;
            float u1r =  FFT_C * (b1r + b1i), u1i = FFT_C * (b1i - b1r);
            float u2r =  b2i,                 u2i = -b2r;
            float u3r = -FFT_C * (b3r - b3i), u3i = -FFT_C * (b3r + b3i);
            float t0r = a0r + a2r, t0i = a0i + a2i;
            float t1r = a1r + a3r, t1i = a1i + a3i;
            float t2r = a0r - a2r, t2i = a0i - a2i;
            float t3r = a1i - a3i, t3i = a3r - a1r;
            float X0r = t0r + t1r, X0i = t0i + t1i;
            float X2r = t2r + t3r, X2i = t2i + t3i;
            float X4r = t0r - t1r, X4i = t0i - t1i;
            float X6r = t2r - t3r, X6i = t2i - t3i;
            float s0r = b0r + u2r, s0i = b0i + u2i;
            float s1r = u1r + u3r, s1i = u1i + u3i;
            float s2r = b0r - u2r, s2i = b0i - u2i;
            float s3r = u1i - u3i, s3i = u3r - u1r;
            float X1r = s0r + s1r, X1i = s0i + s1i;
            float X3r = s2r + s3r, X3i = s2i + s3i;
            float X5r = s0r - s1r, X5i = s0i - s1i;
            float X7r = s2r - s3r, X7i = s2i - s3i;
            SR[p0] = X0r; SI[p0] = X0i;
            if (lm > 0) {
                int tb = q * str;
                float2 w1 = g_tw[tb],     w2 = g_tw[2 * tb], w3 = g_tw[3 * tb];
                float2 w4 = g_tw[4 * tb], w5 = g_tw[5 * tb], w6 = g_tw[6 * tb];
                float2 w7 = g_tw[7 * tb];
                SR[p1] = X1r * w1.x - X1i * w1.y; SI[p1] = X1r * w1.y + X1i * w1.x;
                SR[p2] = X2r * w2.x - X2i * w2.y; SI[p2] = X2r * w2.y + X2i * w2.x;
                SR[p3] = X3r * w3.x - X3i * w3.y; SI[p3] = X3r * w3.y + X3i * w3.x;
                SR[p4] = X4r * w4.x - X4i * w4.y; SI[p4] = X4r * w4.y + X4i * w4.x;
                SR[p5] = X5r * w5.x - X5i * w5.y; SI[p5] = X5r * w5.y + X5i * w5.x;
                SR[p6] = X6r * w6.x - X6i * w6.y; SI[p6] = X6r * w6.y + X6i * w6.x;
                SR[p7] = X7r * w7.x - X7i * w7.y; SI[p7] = X7r * w7.y + X7i * w7.x;
            } else {
                SR[p1] = X1r; SI[p1] = X1i;
                SR[p2] = X2r; SI[p2] = X2i;
                SR[p3] = X3r; SI[p3] = X3i;
                SR[p4] = X4r; SI[p4] = X4i;
                SR[p5] = X5r; SI[p5] = X5i;
                SR[p6] = X6r; SI[p6] = X6i;
                SR[p7] = X7r; SI[p7] = X7i;
            }
        }
        __syncthreads();
    }
}

__device__ __forceinline__ void fft_inv_r8(float* __restrict__ SR, float* __restrict__ SI) {
    #pragma unroll
    for (int s = 0; s < 4; s++) {
        const int lm  = 3 * s;
        const int m   = 1 << lm;
        const int str = 1024 >> lm;
        #pragma unroll
        for (int jj = 0; jj < FFT_R8_IT; jj++) {
            int t = threadIdx.x + jj * FFT_THREADS;
            int q = t & (m - 1);
            int base = ((t >> lm) << (lm + 3)) | q;
            int p0 = PADI(base), p1 = PADI(base + m), p2 = PADI(base + 2 * m),
                p3 = PADI(base + 3 * m), p4 = PADI(base + 4 * m), p5 = PADI(base + 5 * m),
                p6 = PADI(base + 6 * m), p7 = PADI(base + 7 * m);
            float y0r = SR[p0], y0i = SI[p0];
            float y1r = SR[p1], y1i = SI[p1];
            float y2r = SR[p2], y2i = SI[p2];
            float y3r = SR[p3], y3i = SI[p3];
            float y4r = SR[p4], y4i = SI[p4];
            float y5r = SR[p5], y5i = SI[p5];
            float y6r = SR[p6], y6i = SI[p6];
            float y7r = SR[p7], y7i = SI[p7];
            if (lm > 0) {
                int tb = q * str;
                float2 w1 = g_tw[tb],     w2 = g_tw[2 * tb], w3 = g_tw[3 * tb];
                float2 w4 = g_tw[4 * tb], w5 = g_tw[5 * tb], w6 = g_tw[6 * tb];
                float2 w7 = g_tw[7 * tb];
                float cr;
                cr = y1r * w1.x + y1i * w1.y; y1i = y1i * w1.x - y1r * w1.y; y1r = cr;
                cr = y2r * w2.x + y2i * w2.y; y2i = y2i * w2.x - y2r * w2.y; y2r = cr;
                cr = y3r * w3.x + y3i * w3.y; y3i = y3i * w3.x - y3r * w3.y; y3r = cr;
                cr = y4r * w4.x + y4i * w4.y; y4i = y4i * w4.x - y4r * w4.y; y4r = cr;
                cr = y5r * w5.x + y5i * w5.y; y5i = y5i * w5.x - y5r * w5.y; y5r = cr;
                cr = y6r * w6.x + y6i * w6.y; y6i = y6i * w6.x - y6r * w6.y; y6r = cr;
                cr = y7r * w7.x + y7i * w7.y; y7i = y7i * w7.x - y7r * w7.y; y7r = cr;
            }
            float t0r = y0r + y4r, t0i = y0i + y4i;
            float t1r = y2r + y6r, t1i = y2i + y6i;
            float t2r = y0r - y4r, t2i = y0i - y4i;
            float t3r = y6i - y2i, t3i = y2r - y6r;
            float a0r = t0r + t1r, a0i = t0i + t1i;
            float a1r = t2r + t3r, a1i = t2i + t3i;
            float a2r = t0r - t1r, a2i = t0i - t1i;
            float a3r = t2r - t3r, a3i = t2i - t3i;
            float s0r = y1r + y5r, s0i = y1i + y5i;
            float s1r = y3r + y7r, s1i = y3i + y7i;
            float s2r = y1r - y5r, s2i = y1i - y5i;
            float s3r = y7i - y3i, s3i = y3r - y7r;
            float d0r = s0r + s1r, d0i = s0i + s1i;
            float d1r = s2r + s3r, d1i = s2i + s3i;
            float d2r = s0r - s1r, d2i = s0i - s1i;
            float d3r = s2r - s3r, d3i = s2i - s3i;
            float e1r =  FFT_C * (d1r - d1i), e1i = FFT_C * (d1r + d1i);
            float e2r = -d2i,                 e2i = d2r;
            float e3r = -FFT_C * (d3r + d3i), e3i = FFT_C * (d3r - d3i);
            SR[p0] = a0r + d0r; SI[p0] = a0i + d0i;
            SR[p4] = a0r - d0r; SI[p4] = a0i - d0i;
            SR[p1] = a1r + e1r; SI[p1] = a1i + e1i;
            SR[p5] = a1r - e1r; SI[p5] = a1i - e1i;
            SR[p2] = a2r + e2r; SI[p2] = a2i + e2i;
            SR[p6] = a2r - e2r; SI[p6] = a2i - e2i;
            SR[p3] = a3r + e3r; SI[p3] = a3i + e3i;
            SR[p7] = a3r - e3r; SI[p7] = a3i - e3i;
        }
        __syncthreads();
    }
}

// ---------------------------------------------------------------------------
// hfft body: fused load + forward radix-2, radix-8 core, A/B store.
__device__ void hfft_body(float* sm, int c) {
    float* SR = sm;
    float* SI = sm + SM_HALF;
    const int n = c >> 9;
    const int dpair = c & (NPAIR - 1);
    const float* h0 = g_h + ((size_t)n * DDIM + 2 * dpair)     * LSEQ;
    const float* h1 = g_h + ((size_t)n * DDIM + 2 * dpair + 1) * LSEQ;

    for (int i = threadIdx.x; i < LSEQ; i += FFT_THREADS) {
        float v0 = h0[i], v1 = h1[i];
        float2 w = g_tw[i];
        SR[PADI(i)] = v0; SI[PADI(i)] = v1;
        SR[PADI(i + 4096)] = v0 * w.x - v1 * w.y;
        SI[PADI(i + 4096)] = v0 * w.y + v1 * w.x;
    }
    __syncthreads();
    fft_fwd_r8(SR, SI);

    float2* Ao = g_A + (size_t)c * NK;
    float2* Bo = g_B + (size_t)c * NK;
    for (int k = threadIdx.x; k <= LSEQ; k += FFT_THREADS) {
        int p = freq_to_slot(k);
        int q = freq_to_slot((NF - k) & (NF - 1));
        float zpr = SR[PADI(p)], zpi = SI[PADI(p)];
        float zqr = SR[PADI(q)], zqi = SI[PADI(q)];
        float g0r = 0.5f * (zpr + zqr), g0i = 0.5f * (zpi - zqi);
        float g1r = 0.5f * (zpi + zqi), g1i = 0.5f * (zqr - zpr);
        Ao[k] = make_float2(0.5f * (g0r + g1r), 0.5f * (g0i + g1i));
        Bo[k] = make_float2(0.5f * (g0r - g1r), 0.5f * (g0i - g1i));
    }
}

// ---------------------------------------------------------------------------
// Fused launch: hfft (bid < 1024) + gemm_in (bid >= 1024).
#define GI_STAGE 32768
#define GI_SMEM  (3 * GI_STAGE)

__global__ __launch_bounds__(256, 2) void gemm_in_mma(const float* __restrict__ bias)
{
    extern __shared__ char smem[];
    if (blockIdx.x < 2 * NPAIR) {
        hfft_body((float*)smem, blockIdx.x);
        return;
    }
    const int gb = blockIdx.x - 2 * NPAIR;   // 0..1535
    const uint32_t sb = smem_u32(smem);
    const int tid  = threadIdx.x;
    const int lane = tid & 31;
    const int wid  = tid >> 5;
    const int warp_m = wid >> 2;
    const int warp_n = wid & 3;

    const int b   = gb / 768;
    const int rem = gb % 768;
    const int m0  = (rem / 32) * 128;   // od
    const int n0  = (rem % 32) * 128;   // l
    float* C = g_res + (size_t)b * ODIM * LSEQ;

    const int tile = tid >> 6;
    const int tloc = tid & 63;
    const char* gbase;
    if      (tile == 0) gbase = (const char*)g_wh + (size_t)m0 * 2048;
    else if (tile == 1) gbase = (const char*)g_wl + (size_t)m0 * 2048;
    else if (tile == 2) gbase = (const char*)g_uh + (size_t)(b * LSEQ + n0) * 2048;
    else                gbase = (const char*)g_ul + (size_t)(b * LSEQ + n0) * 2048;

    float acc[4][4][4];
    #pragma unroll
    for (int i = 0; i < 4; i++)
        #pragma unroll
        for (int j = 0; j < 4; j++)
            #pragma unroll
            for (int r = 0; r < 4; r++) acc[i][j][r] = 0.0f;

    const int ar  = (lane & 7) + ((lane & 8) ? 8 : 0);
    const int sA  = (ar >> 1) & 3;
    const int a16 = (lane & 16) ? 1 : 0;
    const int br  = lane & 7;
    const int sB  = (br >> 1) & 3;
    const int b16 = (lane & 8) ? 1 : 0;

    #pragma unroll
    for (int p = 0; p < 2; p++) {
        #pragma unroll
        for (int o = 0; o < 8; o++) {
            int idx = tloc + o * 64, row = idx >> 2, c = idx & 3;
            uint32_t dst = sb + p * GI_STAGE + tile * 8192 + row * 64
                         + (((c ^ ((row >> 1) & 3))) << 4);
            CP_ASYNC16(dst, gbase + (size_t)row * 2048 + p * 64 + c * 16);
        }
        CP_COMMIT();
    }

    for (int ch = 0; ch < 32; ch++) {
        CP_WAIT1();
        __syncthreads();
        if (ch + 2 < 32) {
            const int st = (ch + 2) % 3;
            #pragma unroll
            for (int o = 0; o < 8; o++) {
                int idx = tloc + o * 64, row = idx >> 2, c = idx & 3;
                uint32_t dst = sb + st * GI_STAGE + tile * 8192 + row * 64
                             + (((c ^ ((row >> 1) & 3))) << 4);
                CP_ASYNC16(dst, gbase + (size_t)row * 2048 + (ch + 2) * 64 + c * 16);
            }
        }
        CP_COMMIT();

        const uint32_t sbase = sb + (ch % 3) * GI_STAGE;
        #pragma unroll
        for (int k16 = 0; k16 < 2; k16++) {
            uint32_t bh[4][2], bl[4][2];
            #pragma unroll
            for (int j = 0; j < 4; j++) {
                uint32_t rb = sbase + 16384 + (warp_n * 32 + j * 8 + br) * 64
                            + (((k16 * 2 + b16) ^ sB) << 4);
                LDSM_X2(bh[j][0], bh[j][1], rb);
                LDSM_X2(bl[j][0], bl[j][1], rb + 8192);
            }
            uint32_t ah[2][4], al[2][4];
            {
                uint32_t ra = sbase + (warp_m * 64 + ar) * 64
                            + (((k16 * 2 + a16) ^ sA) << 4);
                LDSM_X4(ah[0][0], ah[0][1], ah[0][2], ah[0][3], ra);
                LDSM_X4(al[0][0], al[0][1], al[0][2], al[0][3], ra + 8192);
            }
            #pragma unroll
            for (int i = 0; i < 4; i++) {
                const int cur = i & 1;
                if (i < 3) {
                    const int nxt = cur ^ 1;
                    uint32_t ra = sbase + (warp_m * 64 + (i + 1) * 16 + ar) * 64
                                + (((k16 * 2 + a16) ^ sA) << 4);
                    LDSM_X4(ah[nxt][0], ah[nxt][1], ah[nxt][2], ah[nxt][3], ra);
                    LDSM_X4(al[nxt][0], al[nxt][1], al[nxt][2], al[nxt][3], ra + 8192);
                }
                #pragma unroll
                for (int j = 0; j < 4; j++) {
                    mma_bf16(acc[i][j], ah[cur], bh[j]);
                    mma_bf16(acc[i][j], ah[cur], bl[j]);
                    mma_bf16(acc[i][j], al[cur], bh[j]);
                }
            }
        }
    }

    const int g = lane >> 2;
    const int t = lane & 3;
    #pragma unroll
    for (int i = 0; i < 4; i++) {
        int od0 = m0 + warp_m * 64 + i * 16 + g;
        float bv0 = bias[od0];
        float bv1 = bias[od0 + 8];
        #pragma unroll
        for (int j = 0; j < 4; j++) {
            int l = n0 + warp_n * 32 + j * 8 + t * 2;
            *(float2*)&C[(size_t)od0 * LSEQ + l] =
                make_float2(acc[i][j][0] + bv0, acc[i][j][1] + bv0);
            *(float2*)&C[(size_t)(od0 + 8) * LSEQ + l] =
                make_float2(acc[i][j][2] + bv1, acc[i][j][3] + bv1);
        }
    }
}

// ---------------------------------------------------------------------------
// gemm_out: out[b,l,e] = sum_d v[b,d,l]*w_out[e,d] + b_out[e]
#define GO_STAGE 32768
#define GO_SMEM  (3 * GO_STAGE)

__global__ __launch_bounds__(256, 2) void gemm_out_mma(const float* __restrict__ bias,
                                                       float* __restrict__ O)
{
    extern __shared__ char smem[];
    const uint32_t sb = smem_u32(smem);
    const int tid  = threadIdx.x;
    const int lane = tid & 31;
    const int wid  = tid >> 5;
    const int warp_m = wid >> 2;
    const int warp_n = wid & 3;

    const int b  = blockIdx.z;
    const int m0 = blockIdx.y * 128;   // l
    const int n0 = blockIdx.x * 128;   // e
    float* C = O + (size_t)b * LSEQ * DDIM;

    const int tile = tid >> 6;
    const int tloc = tid & 63;
    const char* gbase;
    if      (tile == 0) gbase = (const char*)g_vh + (size_t)(b * DDIM) * 8192 + (size_t)m0 * 2;
    else if (tile == 1) gbase = (const char*)g_vl + (size_t)(b * DDIM) * 8192 + (size_t)m0 * 2;
    else if (tile == 2) gbase = (const char*)g_oh + (size_t)n0 * 2048;
    else                gbase = (const char*)g_ol + (size_t)n0 * 2048;

    float acc[4][4][4];
    #pragma unroll
    for (int i = 0; i < 4; i++)
        #pragma unroll
        for (int j = 0; j < 4; j++)
            #pragma unroll
            for (int r = 0; r < 4; r++) acc[i][j][r] = 0.0f;

    const int tr  = (lane & 7) + ((lane & 16) ? 8 : 0);
    const int sT  = lane & 7;
    const int t16 = (lane & 8) ? 1 : 0;
    const int br  = lane & 7;
    const int sB  = (br >> 1) & 3;
    const int b16 = (lane & 8) ? 1 : 0;

    #pragma unroll
    for (int p = 0; p < 2; p++) {
        if (tile < 2) {
            #pragma unroll
            for (int o = 0; o < 8; o++) {
                int idx = tloc + o * 64, row = idx >> 4, c16 = idx & 15;
                uint32_t dst = sb + p * GO_STAGE + tile * 8192 + row * 256
                             + (((c16 ^ (row & 7))) << 4);
                CP_ASYNC16(dst, gbase + (size_t)(p * 32 + row) * 8192 + c16 * 16);
            }
        } else {
            #pragma unroll
            for (int o = 0; o < 8; o++) {
                int idx = tloc + o * 64, row = idx >> 2, c = idx & 3;
                uint32_t dst = sb + p * GO_STAGE + (tile - 2) * 8192 + 16384 + row * 64
                             + (((c ^ ((row >> 1) & 3))) << 4);
                CP_ASYNC16(dst, gbase + (size_t)row * 2048 + p * 64 + c * 16);
            }
        }
        CP_COMMIT();
    }

    for (int ch = 0; ch < 32; ch++) {
        CP_WAIT1();
        __syncthreads();
        if (ch + 2 < 32) {
            const int st = (ch + 2) % 3;
            if (tile < 2) {
                #pragma unroll
                for (int o = 0; o < 8; o++) {
                    int idx = tloc + o * 64, row = idx >> 4, c16 = idx & 15;
                    uint32_t dst = sb + st * GO_STAGE + tile * 8192 + row * 256
                                 + (((c16 ^ (row & 7))) << 4);
                    CP_ASYNC16(dst, gbase + (size_t)((ch + 2) * 32 + row) * 8192 + c16 * 16);
                }
            } else {
                #pragma unroll
                for (int o = 0; o < 8; o++) {
                    int idx = tloc + o * 64, row = idx >> 2, c = idx & 3;
                    uint32_t dst = sb + st * GO_STAGE + (tile - 2) * 8192 + 16384 + row * 64
                                 + (((c ^ ((row >> 1) & 3))) << 4);
                    CP_ASYNC16(dst, gbase + (size_t)row * 2048 + (ch + 2) * 64 + c * 16);
                }
            }
        }
        CP_COMMIT();

        const uint32_t sbase = sb + (ch % 3) * GO_STAGE;
        #pragma unroll
        for (int k16 = 0; k16 < 2; k16++) {
            uint32_t bh[4][2], bl[4][2];
            #pragma unroll
            for (int j = 0; j < 4; j++) {
                uint32_t rb = sbase + 16384 + (warp_n * 32 + j * 8 + br) * 64
                            + (((k16 * 2 + b16) ^ sB) << 4);
                LDSM_X2(bh[j][0], bh[j][1], rb);
                LDSM_X2(bl[j][0], bl[j][1], rb + 8192);
            }
            uint32_t ah[2][4], al[2][4];
            {
                int rowd = k16 * 16 + tr;
                uint32_t ra = sbase + rowd * 256 + (((warp_m * 8 + t16) ^ sT) << 4);
                LDSM_X4_T(ah[0][0], ah[0][1], ah[0][2], ah[0][3], ra);
                LDSM_X4_T(al[0][0], al[0][1], al[0][2], al[0][3], ra + 8192);
            }
            #pragma unroll
            for (int i = 0; i < 4; i++) {
                const int cur = i & 1;
                if (i < 3) {
                    const int nxt = cur ^ 1;
                    int rowd = k16 * 16 + tr;
                    uint32_t ra = sbase + rowd * 256
                                + (((warp_m * 8 + (i + 1) * 2 + t16) ^ sT) << 4);
                    LDSM_X4_T(ah[nxt][0], ah[nxt][1], ah[nxt][2], ah[nxt][3], ra);
                    LDSM_X4_T(al[nxt][0], al[nxt][1], al[nxt][2], al[nxt][3], ra + 8192);
                }
                #pragma unroll
                for (int j = 0; j < 4; j++) {
                    mma_bf16(acc[i][j], ah[cur], bh[j]);
                    mma_bf16(acc[i][j], ah[cur], bl[j]);
                    mma_bf16(acc[i][j], al[cur], bh[j]);
                }
            }
        }
    }

    const int g = lane >> 2;
    const int t = lane & 3;
    #pragma unroll
    for (int j = 0; j < 4; j++) {
        int e = n0 + warp_n * 32 + j * 8 + t * 2;
        float bb0 = bias[e];
        float bb1 = bias[e + 1];
        #pragma unroll
        for (int i = 0; i < 4; i++) {
            int l = m0 + warp_m * 64 + i * 16 + g;
            *(float2*)&C[(size_t)l * DDIM + e] =
                make_float2(acc[i][j][0] + bb0, acc[i][j][1] + bb1);
            *(float2*)&C[(size_t)(l + 8) * DDIM + e] =
                make_float2(acc[i][j][2] + bb0, acc[i][j][3] + bb1);
        }
    }
}

// ---------------------------------------------------------------------------
__device__ __forceinline__ float conv3_at(const float* __restrict__ r, int l,
                                          float w0, float w1, float w2, float cb) {
    float left  = (l > 0)        ? r[l - 1] : 0.0f;
    float right = (l < LSEQ - 1) ? r[l + 1] : 0.0f;
    return w0 * left + w1 * r[l] + w2 * right + cb;
}

__global__ __launch_bounds__(FFT_THREADS, 3) void fftconv_kernel(
    const float* __restrict__ cw, const float* __restrict__ cbv)
{
    extern __shared__ float sm[];
    float* SR = sm;
    float* SI = sm + SM_HALF;
    const int c = blockIdx.x;
    const int b = c >> 9;
    const int dpair = c & (NPAIR - 1);
    const int ch0 = 2 * dpair, ch1 = ch0 + 1;
    const float inv = 1.0f / (float)NF;

    // Fused: load v (conv3 of order-2 row) + forward radix-2 (zero-padded)
    {
        const float* r2a = g_res + ((size_t)(b * 3 + 2) * DDIM + ch0) * LSEQ;
        const float* r2b = g_res + ((size_t)(b * 3 + 2) * DDIM + ch1) * LSEQ;
        const int oa = 2 * DDIM + ch0, ob = 2 * DDIM + ch1;
        float w0a = cw[oa * 3], w1a = cw[oa * 3 + 1], w2a = cw[oa * 3 + 2], cba = cbv[oa];
        float w0b = cw[ob * 3], w1b = cw[ob * 3 + 1], w2b = cw[ob * 3 + 2], cbb = cbv[ob];
        for (int i = threadIdx.x; i < LSEQ; i += FFT_THREADS) {
            float v0 = conv3_at(r2a, i, w0a, w1a, w2a, cba);
            float v1 = conv3_at(r2b, i, w0b, w1b, w2b, cbb);
            float2 w = g_tw[i];
            SR[PADI(i)] = v0; SI[PADI(i)] = v1;
            SR[PADI(i + 4096)] = v0 * w.x - v1 * w.y;
            SI[PADI(i + 4096)] = v0 * w.y + v1 * w.x;
        }
    }
    __syncthreads();

    #pragma unroll 1
    for (int n = 0; n < 2; n++) {
        fft_fwd_r8(SR, SI);

        const float2* Ap = g_A + ((size_t)n * NPAIR + dpair) * NK;
        const float2* Bp = g_B + ((size_t)n * NPAIR + dpair) * NK;
        for (int k = threadIdx.x; k <= LSEQ; k += FFT_THREADS) {
            int p = freq_to_slot(k);
            int q = freq_to_slot((NF - k) & (NF - 1));
            int ip = PADI(p), iq = PADI(q);
            float zr = SR[ip], zi = SI[ip];
            float wr = SR[iq], wi = SI[iq];
            float2 a  = Ap[k];
            float2 bb = Bp[k];
            float ypr = a.x * zr - a.y * zi + bb.x * wr + bb.y * wi;
            float ypi = a.x * zi + a.y * zr + bb.y * wr - bb.x * wi;
            SR[ip] = ypr; SI[ip] = ypi;
            if (q != p) {
                float yqr = a.x * wr + a.y * wi + bb.x * zr - bb.y * zi;
                float yqi = a.x * wi - a.y * wr - bb.x * zi - bb.y * zr;
                SR[iq] = yqr; SI[iq] = yqi;
            }
        }
        __syncthreads();

        fft_inv_r8(SR, SI);

        const float* rna = g_res + ((size_t)(b * 3 + n) * DDIM + ch0) * LSEQ;
        const float* rnb = g_res + ((size_t)(b * 3 + n) * DDIM + ch1) * LSEQ;
        const int oa = n * DDIM + ch0, ob = n * DDIM + ch1;
        float w0a = cw[oa * 3], w1a = cw[oa * 3 + 1], w2a = cw[oa * 3 + 2], cba = cbv[oa];
        float w0b = cw[ob * 3], w1b = cw[ob * 3 + 1], w2b = cw[ob * 3 + 2], cbb = cbv[ob];

        if (n == 0) {
            // Fused: inverse radix-2 (lower) + gate + next forward radix-2
            for (int j = threadIdx.x; j < LSEQ; j += FFT_THREADS) {
                int i0 = PADI(j), i1 = PADI(j + 4096);
                float2 w = g_tw[j];
                float br2 = SR[i1], bi2 = SI[i1];
                float ar = SR[i0] + (br2 * w.x + bi2 * w.y);
                float ai = SI[i0] + (bi2 * w.x - br2 * w.y);
                float yr = ar * inv * conv3_at(rna, j, w0a, w1a, w2a, cba);
                float yi = ai * inv * conv3_at(rnb, j, w0b, w1b, w2b, cbb);
                SR[i0] = yr; SI[i0] = yi;
                SR[i1] = yr * w.x - yi * w.y;
                SI[i1] = yr * w.y + yi * w.x;
            }
            __syncthreads();
        } else {
            // Fused: inverse radix-2 (lower) + gate + bf16 hi/lo pack + store
            uint32_t* vh0 = g_vh + ((size_t)(b * DDIM + ch0)) * (LSEQ / 2);
            uint32_t* vl0 = g_vl + ((size_t)(b * DDIM + ch0)) * (LSEQ / 2);
            uint32_t* vh1 = g_vh + ((size_t)(b * DDIM + ch1)) * (LSEQ / 2);
            uint32_t* vl1 = g_vl + ((size_t)(b * DDIM + ch1)) * (LSEQ / 2);
            for (int l2 = threadIdx.x; l2 < LSEQ / 2; l2 += FFT_THREADS) {
                float yv[2][2];
                #pragma unroll
                for (int e = 0; e < 2; e++) {
                    int j = 2 * l2 + e;
                    int i0 = PADI(j), i1 = PADI(j + 4096);
                    float2 w = g_tw[j];
                    float br2 = SR[i1], bi2 = SI[i1];
                    float ar = SR[i0] + (br2 * w.x + bi2 * w.y);
                    float ai = SI[i0] + (bi2 * w.x - br2 * w.y);
                    yv[0][e] = ar * inv * conv3_at(rna, j, w0a, w1a, w2a, cba);
                    yv[1][e] = ai * inv * conv3_at(rnb, j, w0b, w1b, w2b, cbb);
                }
                vh0[l2] = pack_hi(yv[0][0], yv[0][1]); vl0[l2] = pack_lo(yv[0][0], yv[0][1]);
                vh1[l2] = pack_hi(yv[1][0], yv[1][1]); vl1[l2] = pack_lo(yv[1][0], yv[1][1]);
            }
        }
    }
}

// ---------------------------------------------------------------------------
extern "C" void kernel_launch(void* const* d_in, const int* in_sizes, int n_in,
                              void* d_out, int out_size)
{
    const float* u          = (const float*)d_in[0];
    const float* w_in       = (const float*)d_in[1];
    const float* b_in       = (const float*)d_in[2];
    const float* conv_w     = (const float*)d_in[3];
    const float* conv_b     = (const float*)d_in[4];
    const float* w1         = (const float*)d_in[5];
    const float* b1         = (const float*)d_in[6];
    const float* w2         = (const float*)d_in[7];
    const float* b2         = (const float*)d_in[8];
    const float* filt_bias  = (const float*)d_in[9];
    const float* filt_decay = (const float*)d_in[10];
    const float* w_out      = (const float*)d_in[11];
    const float* b_out      = (const float*)d_in[12];
    float* out = (float*)d_out;

    static bool attr_set = false;
    if (!attr_set) {
        cudaFuncSetAttribute(fftconv_kernel, cudaFuncAttributeMaxDynamicSharedMemorySize, FFT_SMEM);
        cudaFuncSetAttribute(gemm_in_mma,    cudaFuncAttributeMaxDynamicSharedMemorySize, GI_SMEM);
        cudaFuncSetAttribute(gemm_out_mma,   cudaFuncAttributeMaxDynamicSharedMemorySize, GO_SMEM);
        cudaFuncSetAttribute(filter_gemm,    cudaFuncAttributeMaxDynamicSharedMemorySize, 65536);
        attr_set = true;
    }

    // 1: prep — conversions + twiddles + sact
    prep_kernel<<<PREP_GRID, 256>>>(w_in, u, w_out, w1, b1);
    // 2: filter GEMM (produces g_h)
    filter_gemm<<<512, 256, 65536>>>(w2, b2, filt_bias, filt_decay);
    // 3: hfft (1024 CTAs) fused with gemm_in (1536 CTAs)
    gemm_in_mma<<<2 * NPAIR + 1536, 256, GI_SMEM>>>(b_in);
    // 4: fftconv (profiled slot, 3 CTAs/SM)
    fftconv_kernel<<<BSZ * NPAIR, FFT_THREADS, FFT_SMEM>>>(conv_w, conv_b);
    // 5: output GEMM
    gemm_out_mma<<<dim3(DDIM / 128, LSEQ / 128, BSZ), 256, GO_SMEM>>>(b_out, out);
}

// round 15
// speedup vs baseline: 1.5539x; 1.5539x over previous
#include <cuda_runtime.h>
#include <cuda_bf16.h>
#include <cstdint>
#include <cstddef>

// ---------------------------------------------------------------------------
// Hyena operator: B=2, L=4096, D=1024, ORDER=2, OD=3072
// Round 15: revert R14 fusions (regression) back to R13 structure;
// prep_kernel sact branch optimized (smem pe + w1 cache).
// ---------------------------------------------------------------------------

#define LSEQ 4096
#define NF   8192
#define DDIM 1024
#define ODIM 3072
#define BSZ  2
#define NPAIR 512
#define NK    4100
#define FFT_THREADS 256
#define FFT_ZP_IT (4096 / FFT_THREADS)
#define FFT_R8_IT (1024 / FFT_THREADS)
#define PADI(i) ((i) + ((i) >> 5))
#define SM_HALF 8448
#define FFT_SMEM (2 * SM_HALF * 4)

// Scratch (device .bss — allocation-free)
__device__ float  g_res[(size_t)BSZ * ODIM * LSEQ];
__device__ float  g_h  [(size_t)2   * DDIM * LSEQ];
__device__ float  g_sact[(size_t)LSEQ * 64];
__device__ float2 g_A  [(size_t)2 * NPAIR * NK];
__device__ float2 g_B  [(size_t)2 * NPAIR * NK];
__device__ float2 g_tw [NF];
// packed bf16 hi/lo operands (uint32 = 2 bf16)
__device__ uint32_t g_wh[(size_t)ODIM * DDIM / 2];
__device__ uint32_t g_wl[(size_t)ODIM * DDIM / 2];
__device__ uint32_t g_uh[(size_t)BSZ * LSEQ * DDIM / 2];
__device__ uint32_t g_ul[(size_t)BSZ * LSEQ * DDIM / 2];
__device__ uint32_t g_oh[(size_t)DDIM * DDIM / 2];
__device__ uint32_t g_ol[(size_t)DDIM * DDIM / 2];
__device__ uint32_t g_vh[(size_t)BSZ * DDIM * LSEQ / 2];
__device__ uint32_t g_vl[(size_t)BSZ * DDIM * LSEQ / 2];

// ---------------------------------------------------------------------------
__device__ __forceinline__ uint32_t smem_u32(const void* p) {
    uint32_t a;
    asm("{ .reg .u64 t; cvta.to.shared.u64 t, %1; cvt.u32.u64 %0, t; }" : "=r"(a) : "l"(p));
    return a;
}

#define LDSM_X4(r0, r1, r2, r3, addr) \
    asm volatile("ldmatrix.sync.aligned.m8n8.x4.shared.b16 {%0,%1,%2,%3}, [%4];" \
                 : "=r"(r0), "=r"(r1), "=r"(r2), "=r"(r3) : "r"(addr))
#define LDSM_X4_T(r0, r1, r2, r3, addr) \
    asm volatile("ldmatrix.sync.aligned.m8n8.x4.trans.shared.b16 {%0,%1,%2,%3}, [%4];" \
                 : "=r"(r0), "=r"(r1), "=r"(r2), "=r"(r3) : "r"(addr))
#define LDSM_X2(r0, r1, addr) \
    asm volatile("ldmatrix.sync.aligned.m8n8.x2.shared.b16 {%0,%1}, [%2];" \
                 : "=r"(r0), "=r"(r1) : "r"(addr))
#define CP_ASYNC16(dst, src) \
    asm volatile("cp.async.cg.shared.global [%0], [%1], 16;" :: "r"(dst), "l"(src))
#define CP_COMMIT() asm volatile("cp.async.commit_group;" ::: "memory")
#define CP_WAIT1()  asm volatile("cp.async.wait_group 1;" ::: "memory")

__device__ __forceinline__ void mma_bf16(float* c, const uint32_t* a, const uint32_t* b) {
    asm volatile(
        "mma.sync.aligned.m16n8k16.row.col.f32.bf16.bf16.f32 "
        "{%0,%1,%2,%3}, {%4,%5,%6,%7}, {%8,%9}, {%0,%1,%2,%3};"
        : "+f"(c[0]), "+f"(c[1]), "+f"(c[2]), "+f"(c[3])
        : "r"(a[0]), "r"(a[1]), "r"(a[2]), "r"(a[3]), "r"(b[0]), "r"(b[1]));
}

__device__ __forceinline__ uint32_t pack_hi(float x, float y) {
    __nv_bfloat16 hx = __float2bfloat16(x);
    __nv_bfloat16 hy = __float2bfloat16(y);
    return (uint32_t)__bfloat16_as_ushort(hx) | ((uint32_t)__bfloat16_as_ushort(hy) << 16);
}
__device__ __forceinline__ uint32_t pack_lo(float x, float y) {
    __nv_bfloat16 hx = __float2bfloat16(x);
    __nv_bfloat16 hy = __float2bfloat16(y);
    __nv_bfloat16 lx = __float2bfloat16(x - __bfloat162float(hx));
    __nv_bfloat16 ly = __float2bfloat16(y - __bfloat162float(hy));
    return (uint32_t)__bfloat16_as_ushort(lx) | ((uint32_t)__bfloat16_as_ushort(ly) << 16);
}

// mixed-radix [2,8,8,8,8] frequency -> slot map
__device__ __forceinline__ int freq_to_slot(int k) {
    return (k & 1) * 4096 + ((k >> 1) & 7) * 512 + ((k >> 4) & 7) * 64
         + ((k >> 7) & 7) * 8 + ((k >> 10) & 7);
}

// ---------------------------------------------------------------------------
// prep_kernel: sact + 3x cvt_split + twiddles, grid-partitioned.
// sact branch uses smem-cached pe + w1 (132 sinf/block instead of 8448).
#define PREP_SACT  1024
#define PREP_WIN   6144
#define PREP_U     16384
#define PREP_WOUT  2048
#define PREP_INIT  32
#define PREP_GRID  (PREP_SACT + PREP_WIN + PREP_U + PREP_WOUT + PREP_INIT)

__global__ __launch_bounds__(256) void prep_kernel(
    const float* __restrict__ w_in, const float* __restrict__ u,
    const float* __restrict__ w_out,
    const float* __restrict__ w1, const float* __restrict__ b1)
{
    __shared__ float pe[4][33];
    __shared__ float w1s[64 * 33];
    const int bid = blockIdx.x;
    const int tid = threadIdx.x;
    if (bid < PREP_SACT) {
        // block covers l = bid*4 .. bid*4+3, u = 0..63
        for (int i = tid; i < 64 * 33; i += 256) w1s[i] = w1[i];
        if (tid < 132) {
            int li = tid / 33, j = tid % 33;
            float t = (float)(bid * 4 + li) * (1.0f / (float)(LSEQ - 1));
            pe[li][j] = sinf(t * (float)j * 10.0f);
        }
        __syncthreads();
        const int li = tid >> 6;
        const int un = tid & 63;
        float z = b1[un];
        #pragma unroll
        for (int j = 0; j < 33; j++) z += pe[li][j] * w1s[un * 33 + j];
        g_sact[bid * 256 + tid] = sinf(10.0f * z);
    } else if (bid < PREP_SACT + PREP_WIN) {
        int i = (bid - PREP_SACT) * 256 + tid;
        float2 v = ((const float2*)w_in)[i];
        g_wh[i] = pack_hi(v.x, v.y);
        g_wl[i] = pack_lo(v.x, v.y);
    } else if (bid < PREP_SACT + PREP_WIN + PREP_U) {
        int i = (bid - PREP_SACT - PREP_WIN) * 256 + tid;
        float2 v = ((const float2*)u)[i];
        g_uh[i] = pack_hi(v.x, v.y);
        g_ul[i] = pack_lo(v.x, v.y);
    } else if (bid < PREP_SACT + PREP_WIN + PREP_U + PREP_WOUT) {
        int i = (bid - PREP_SACT - PREP_WIN - PREP_U) * 256 + tid;
        float2 v = ((const float2*)w_out)[i];
        g_oh[i] = pack_hi(v.x, v.y);
        g_ol[i] = pack_lo(v.x, v.y);
    } else {
        int i = (bid - PREP_SACT - PREP_WIN - PREP_U - PREP_WOUT) * 256 + tid;
        double ang = -2.0 * 3.141592653589793238462643 * (double)i / (double)NF;
        g_tw[i] = make_float2((float)cos(ang), (float)sin(ang));
    }
}

// ---------------------------------------------------------------------------
// filter_gemm: g_h[o][l] (standalone launch)
__global__ __launch_bounds__(256) void filter_gemm(
    const float* __restrict__ w2, const float* __restrict__ b2,
    const float* __restrict__ fb, const float* __restrict__ fd)
{
    extern __shared__ float fsm[];
    float (*As)[128] = (float(*)[128])fsm;
    float (*Bs)[128] = (float(*)[128])(fsm + 64 * 128);
    const int l0 = (blockIdx.x & 31) * 128;
    const int o0 = (blockIdx.x >> 5) * 128;
    const int tid = threadIdx.x;
    const int tm = tid >> 4;
    const int tn = tid & 15;
    const int lrow = tid >> 1;
    const int lk   = (tid & 1) * 32;

    #pragma unroll
    for (int f = 0; f < 8; f++) {
        float4 a = *(const float4*)&w2[(size_t)(o0 + lrow) * 64 + lk + f * 4];
        As[lk + f * 4 + 0][lrow] = a.x; As[lk + f * 4 + 1][lrow] = a.y;
        As[lk + f * 4 + 2][lrow] = a.z; As[lk + f * 4 + 3][lrow] = a.w;
        float4 s = *(const float4*)&g_sact[(size_t)(l0 + lrow) * 64 + lk + f * 4];
        Bs[lk + f * 4 + 0][lrow] = s.x; Bs[lk + f * 4 + 1][lrow] = s.y;
        Bs[lk + f * 4 + 2][lrow] = s.z; Bs[lk + f * 4 + 3][lrow] = s.w;
    }
    __syncthreads();

    float acc[8][8];
    #pragma unroll
    for (int i = 0; i < 8; i++)
        #pragma unroll
        for (int j = 0; j < 8; j++) acc[i][j] = 0.0f;

    #pragma unroll
    for (int k = 0; k < 64; k++) {
        float4 ra0 = *(const float4*)&As[k][tm * 8];
        float4 ra1 = *(const float4*)&As[k][tm * 8 + 4];
        float4 rb0 = *(const float4*)&Bs[k][tn * 8];
        float4 rb1 = *(const float4*)&Bs[k][tn * 8 + 4];
        float ra[8] = {ra0.x, ra0.y, ra0.z, ra0.w, ra1.x, ra1.y, ra1.z, ra1.w};
        float rb[8] = {rb0.x, rb0.y, rb0.z, rb0.w, rb1.x, rb1.y, rb1.z, rb1.w};
        #pragma unroll
        for (int i = 0; i < 8; i++)
            #pragma unroll
            for (int j = 0; j < 8; j++) acc[i][j] += ra[i] * rb[j];
    }

    #pragma unroll
    for (int i = 0; i < 8; i++) {
        int o = o0 + tm * 8 + i;
        float ed  = expf(fd[o]);
        float bb  = b2[o];
        float fbo = fb[o];
        float v[8];
        #pragma unroll
        for (int j = 0; j < 8; j++) {
            int l = l0 + tn * 8 + j;
            float t = (float)l * (1.0f / (float)(LSEQ - 1));
            v[j] = ((acc[i][j] + bb) * expf(-ed * t) + fbo) * (1.0f / (float)LSEQ);
        }
        *(float4*)&g_h[(size_t)o * LSEQ + l0 + tn * 8]     = make_float4(v[0], v[1], v[2], v[3]);
        *(float4*)&g_h[(size_t)o * LSEQ + l0 + tn * 8 + 4] = make_float4(v[4], v[5], v[6], v[7]);
    }
}

// ---------------------------------------------------------------------------
// FFT: 8192-pt, FFT_THREADS threads, split re/im padded smem, radix [2,8,8,8,8].
#define FFT_C 0.70710678118654752f

__device__ __forceinline__ void fft_fwd_zp(float* __restrict__ SR, float* __restrict__ SI) {
    #pragma unroll
    for (int jj = 0; jj < FFT_ZP_IT; jj++) {
        int j  = threadIdx.x + jj * FFT_THREADS;
        int i0 = PADI(j), i1 = PADI(j + 4096);
        float ar = SR[i0], ai = SI[i0];
        float2 w = g_tw[j];
        SR[i1] = ar * w.x - ai * w.y;
        SI[i1] = ar * w.y + ai * w.x;
    }
    __syncthreads();
    #pragma unroll
    for (int s = 0; s < 4; s++) {
        const int lm  = 9 - 3 * s;
        const int m   = 1 << lm;
        const int str = 1024 >> lm;
        #pragma unroll
        for (int jj = 0; jj < FFT_R8_IT; jj++) {
            int t = threadIdx.x + jj * FFT_THREADS;
            int q = t & (m - 1);
            int base = ((t >> lm) << (lm + 3)) | q;
            int p0 = PADI(base), p1 = PADI(base + m), p2 = PADI(base + 2 * m),
                p3 = PADI(base + 3 * m), p4 = PADI(base + 4 * m), p5 = PADI(base + 5 * m),
                p6 = PADI(base + 6 * m), p7 = PADI(base + 7 * m);
            float x0r = SR[p0], x0i = SI[p0];
            float x1r = SR[p1], x1i = SI[p1];
            float x2r = SR[p2], x2i = SI[p2];
            float x3r = SR[p3], x3i = SI[p3];
            float x4r = SR[p4], x4i = SI[p4];
            float x5r = SR[p5], x5i = SI[p5];
            float x6r = SR[p6], x6i = SI[p6];
            float x7r = SR[p7], x7i = SI[p7];
            float a0r = x0r + x4r, a0i = x0i + x4i;
            float a1r = x1r + x5r, a1i = x1i + x5i;
            float a2r = x2r + x6r, a2i = x2i + x6i;
            float a3r = x3r + x7r, a3i = x3i + x7i;
            float b0r = x0r - x4r, b0i = x0i - x4i;
            float b1r = x1r - x5r, b1i = x1i - x5i;
            float b2r = x2r - x6r, b2i = x2i - x6i;
            float b3r = x3r - x7r, b3i = x3i - x7i;
            float u1r =  FFT_C * (b1r + b1i), u1i = FFT_C * (b1i - b1r);
            float u2r =  b2i,                 u2i = -b2r;
            float u3r = -FFT_C * (b3r - b3i), u3i = -FFT_C * (b3r + b3i);
            float t0r = a0r + a2r, t0i = a0i + a2i;
            float t1r = a1r + a3r, t1i = a1i + a3i;
            float t2r = a0r - a2r, t2i = a0i - a2i;
            float t3r = a1i - a3i, t3i = a3r - a1r;
            float X0r = t0r + t1r, X0i = t0i + t1i;
            float X2r = t2r + t3r, X2i = t2i + t3i;
            float X4r = t0r - t1r, X4i = t0i - t1i;
            float X6r = t2r - t3r, X6i = t2i - t3i;
            float s0r = b0r + u2r, s0i = b0i + u2i;
            float s1r = u1r + u3r, s1i = u1i + u3i;
            float s2r = b0r - u2r, s2i = b0i - u2i;
            float s3r = u1i - u3i, s3i = u3r - u1r;
            float X1r = s0r + s1r, X1i = s0i + s1i;
            float X3r = s2r + s3r, X3i = s2i + s3i;
            float X5r = s0r - s1r, X5i = s0i - s1i;
            float X7r = s2r - s3r, X7i = s2i - s3i;
            SR[p0] = X0r; SI[p0] = X0i;
            if (lm > 0) {
                int tb = q * str;
                float2 w1 = g_tw[tb],     w2 = g_tw[2 * tb], w3 = g_tw[3 * tb];
                float2 w4 = g_tw[4 * tb], w5 = g_tw[5 * tb], w6 = g_tw[6 * tb];
                float2 w7 = g_tw[7 * tb];
                SR[p1] = X1r * w1.x - X1i * w1.y; SI[p1] = X1r * w1.y + X1i * w1.x;
                SR[p2] = X2r * w2.x - X2i * w2.y; SI[p2] = X2r * w2.y + X2i * w2.x;
                SR[p3] = X3r * w3.x - X3i * w3.y; SI[p3] = X3r * w3.y + X3i * w3.x;
                SR[p4] = X4r * w4.x - X4i * w4.y; SI[p4] = X4r * w4.y + X4i * w4.x;
                SR[p5] = X5r * w5.x - X5i * w5.y; SI[p5] = X5r * w5.y + X5i * w5.x;
                SR[p6] = X6r * w6.x - X6i * w6.y; SI[p6] = X6r * w6.y + X6i * w6.x;
                SR[p7] = X7r * w7.x - X7i * w7.y; SI[p7] = X7r * w7.y + X7i * w7.x;
            } else {
                SR[p1] = X1r; SI[p1] = X1i;
                SR[p2] = X2r; SI[p2] = X2i;
                SR[p3] = X3r; SI[p3] = X3i;
                SR[p4] = X4r; SI[p4] = X4i;
                SR[p5] = X5r; SI[p5] = X5i;
                SR[p6] = X6r; SI[p6] = X6i;
                SR[p7] = X7r; SI[p7] = X7i;
            }
        }
        __syncthreads();
    }
}

__device__ __forceinline__ void fft_inv_half(float* __restrict__ SR, float* __restrict__ SI) {
    #pragma unroll
    for (int s = 0; s < 4; s++) {
        const int lm  = 3 * s;
        const int m   = 1 << lm;
        const int str = 1024 >> lm;
        #pragma unroll
        for (int jj = 0; jj < FFT_R8_IT; jj++) {
            int t = threadIdx.x + jj * FFT_THREADS;
            int q = t & (m - 1);
            int base = ((t >> lm) << (lm + 3)) | q;
            int p0 = PADI(base), p1 = PADI(base + m), p2 = PADI(base + 2 * m),
                p3 = PADI(base + 3 * m), p4 = PADI(base + 4 * m), p5 = PADI(base + 5 * m),
                p6 = PADI(base + 6 * m), p7 = PADI(base + 7 * m);
            float y0r = SR[p0], y0i = SI[p0];
            float y1r = SR[p1], y1i = SI[p1];
            float y2r = SR[p2], y2i = SI[p2];
            float y3r = SR[p3], y3i = SI[p3];
            float y4r = SR[p4], y4i = SI[p4];
            float y5r = SR[p5], y5i = SI[p5];
            float y6r = SR[p6], y6i = SI[p6];
            float y7r = SR[p7], y7i = SI[p7];
            if (lm > 0) {
                int tb = q * str;
                float2 w1 = g_tw[tb],     w2 = g_tw[2 * tb], w3 = g_tw[3 * tb];
                float2 w4 = g_tw[4 * tb], w5 = g_tw[5 * tb], w6 = g_tw[6 * tb];
                float2 w7 = g_tw[7 * tb];
                float cr;
                cr = y1r * w1.x + y1i * w1.y; y1i = y1i * w1.x - y1r * w1.y; y1r = cr;
                cr = y2r * w2.x + y2i * w2.y; y2i = y2i * w2.x - y2r * w2.y; y2r = cr;
                cr = y3r * w3.x + y3i * w3.y; y3i = y3i * w3.x - y3r * w3.y; y3r = cr;
                cr = y4r * w4.x + y4i * w4.y; y4i = y4i * w4.x - y4r * w4.y; y4r = cr;
                cr = y5r * w5.x + y5i * w5.y; y5i = y5i * w5.x - y5r * w5.y; y5r = cr;
                cr = y6r * w6.x + y6i * w6.y; y6i = y6i * w6.x - y6r * w6.y; y6r = cr;
                cr = y7r * w7.x + y7i * w7.y; y7i = y7i * w7.x - y7r * w7.y; y7r = cr;
            }
            float t0r = y0r + y4r, t0i = y0i + y4i;
            float t1r = y2r + y6r, t1i = y2i + y6i;
            float t2r = y0r - y4r, t2i = y0i - y4i;
            float t3r = y6i - y2i, t3i = y2r - y6r;
            float a0r = t0r + t1r, a0i = t0i + t1i;
            float a1r = t2r + t3r, a1i = t2i + t3i;
            float a2r = t0r - t1r, a2i = t0i - t1i;
            float a3r = t2r - t3r, a3i = t2i - t3i;
            float s0r = y1r + y5r, s0i = y1i + y5i;
            float s1r = y3r + y7r, s1i = y3i + y7i;
            float s2r = y1r - y5r, s2i = y1i - y5i;
            float s3r = y7i - y3i, s3i = y3r - y7r;
            float d0r = s0r + s1r, d0i = s0i + s1i;
            float d1r = s2r + s3r, d1i = s2i + s3i;
            float d2r = s0r - s1r, d2i = s0i - s1i;
            float d3r = s2r - s3r, d3i = s2i - s3i;
            float e1r =  FFT_C * (d1r - d1i), e1i = FFT_C * (d1r + d1i);
            float e2r = -d2i,                 e2i = d2r;
            float e3r = -FFT_C * (d3r + d3i), e3i = FFT_C * (d3r - d3i);
            SR[p0] = a0r + d0r; SI[p0] = a0i + d0i;
            SR[p4] = a0r - d0r; SI[p4] = a0i - d0i;
            SR[p1] = a1r + e1r; SI[p1] = a1i + e1i;
            SR[p5] = a1r - e1r; SI[p5] = a1i - e1i;
            SR[p2] = a2r + e2r; SI[p2] = a2i + e2i;
            SR[p6] = a2r - e2r; SI[p6] = a2i - e2i;
            SR[p3] = a3r + e3r; SI[p3] = a3i + e3i;
            SR[p7] = a3r - e3r; SI[p7] = a3i - e3i;
        }
        __syncthreads();
    }
    #pragma unroll
    for (int jj = 0; jj < FFT_ZP_IT; jj++) {
        int j  = threadIdx.x + jj * FFT_THREADS;
        int i0 = PADI(j), i1 = PADI(j + 4096);
        float2 w = g_tw[j];
        float br = SR[i1], bi = SI[i1];
        float tr = br * w.x + bi * w.y;
        float ti = bi * w.x - br * w.y;
        SR[i0] += tr; SI[i0] += ti;
    }
    __syncthreads();
}

// ---------------------------------------------------------------------------
// hfft body: pair-packed H spectra -> A/B tables (k-indexed)
__device__ void hfft_body(float* sm, int c) {
    float* SR = sm;
    float* SI = sm + SM_HALF;
    const int n = c >> 9;
    const int dpair = c & (NPAIR - 1);
    const float* h0 = g_h + ((size_t)n * DDIM + 2 * dpair)     * LSEQ;
    const float* h1 = g_h + ((size_t)n * DDIM + 2 * dpair + 1) * LSEQ;

    for (int i = threadIdx.x; i < LSEQ; i += FFT_THREADS) {
        SR[PADI(i)] = h0[i]; SI[PADI(i)] = h1[i];
    }
    __syncthreads();
    fft_fwd_zp(SR, SI);

    float2* Ao = g_A + (size_t)c * NK;
    float2* Bo = g_B + (size_t)c * NK;
    for (int k = threadIdx.x; k <= LSEQ; k += FFT_THREADS) {
        int p = freq_to_slot(k);
        int q = freq_to_slot((NF - k) & (NF - 1));
        float zpr = SR[PADI(p)], zpi = SI[PADI(p)];
        float zqr = SR[PADI(q)], zqi = SI[PADI(q)];
        float g0r = 0.5f * (zpr + zqr), g0i = 0.5f * (zpi - zqi);
        float g1r = 0.5f * (zpi + zqi), g1i = 0.5f * (zqr - zpr);
        Ao[k] = make_float2(0.5f * (g0r + g1r), 0.5f * (g0i + g1i));
        Bo[k] = make_float2(0.5f * (g0r - g1r), 0.5f * (g0i - g1i));
    }
}

// ---------------------------------------------------------------------------
// Fused launch: hfft (bid < 1024) + gemm_in (bid >= 1024).
#define GI_STAGE 32768
#define GI_SMEM  (3 * GI_STAGE)

__global__ __launch_bounds__(256, 2) void gemm_in_mma(const float* __restrict__ bias)
{
    extern __shared__ char smem[];
    if (blockIdx.x < 2 * NPAIR) {
        hfft_body((float*)smem, blockIdx.x);
        return;
    }
    const int gb = blockIdx.x - 2 * NPAIR;   // 0..1535
    const uint32_t sb = smem_u32(smem);
    const int tid  = threadIdx.x;
    const int lane = tid & 31;
    const int wid  = tid >> 5;
    const int warp_m = wid >> 2;
    const int warp_n = wid & 3;

    const int b   = gb / 768;
    const int rem = gb % 768;
    const int m0  = (rem / 32) * 128;   // od
    const int n0  = (rem % 32) * 128;   // l
    float* C = g_res + (size_t)b * ODIM * LSEQ;

    const int tile = tid >> 6;
    const int tloc = tid & 63;
    const char* gbase;
    if      (tile == 0) gbase = (const char*)g_wh + (size_t)m0 * 2048;
    else if (tile == 1) gbase = (const char*)g_wl + (size_t)m0 * 2048;
    else if (tile == 2) gbase = (const char*)g_uh + (size_t)(b * LSEQ + n0) * 2048;
    else                gbase = (const char*)g_ul + (size_t)(b * LSEQ + n0) * 2048;

    float acc[4][4][4];
    #pragma unroll
    for (int i = 0; i < 4; i++)
        #pragma unroll
        for (int j = 0; j < 4; j++)
            #pragma unroll
            for (int r = 0; r < 4; r++) acc[i][j][r] = 0.0f;

    const int ar  = (lane & 7) + ((lane & 8) ? 8 : 0);
    const int sA  = (ar >> 1) & 3;
    const int a16 = (lane & 16) ? 1 : 0;
    const int br  = lane & 7;
    const int sB  = (br >> 1) & 3;
    const int b16 = (lane & 8) ? 1 : 0;

    #pragma unroll
    for (int p = 0; p < 2; p++) {
        #pragma unroll
        for (int o = 0; o < 8; o++) {
            int idx = tloc + o * 64, row = idx >> 2, c = idx & 3;
            uint32_t dst = sb + p * GI_STAGE + tile * 8192 + row * 64
                         + (((c ^ ((row >> 1) & 3))) << 4);
            CP_ASYNC16(dst, gbase + (size_t)row * 2048 + p * 64 + c * 16);
        }
        CP_COMMIT();
    }

    for (int ch = 0; ch < 32; ch++) {
        CP_WAIT1();
        __syncthreads();
        if (ch + 2 < 32) {
            const int st = (ch + 2) % 3;
            #pragma unroll
            for (int o = 0; o < 8; o++) {
                int idx = tloc + o * 64, row = idx >> 2, c = idx & 3;
                uint32_t dst = sb + st * GI_STAGE + tile * 8192 + row * 64
                             + (((c ^ ((row >> 1) & 3))) << 4);
                CP_ASYNC16(dst, gbase + (size_t)row * 2048 + (ch + 2) * 64 + c * 16);
            }
        }
        CP_COMMIT();

        const uint32_t sbase = sb + (ch % 3) * GI_STAGE;
        #pragma unroll
        for (int k16 = 0; k16 < 2; k16++) {
            uint32_t bh[4][2], bl[4][2];
            #pragma unroll
            for (int j = 0; j < 4; j++) {
                uint32_t rb = sbase + 16384 + (warp_n * 32 + j * 8 + br) * 64
                            + (((k16 * 2 + b16) ^ sB) << 4);
                LDSM_X2(bh[j][0], bh[j][1], rb);
                LDSM_X2(bl[j][0], bl[j][1], rb + 8192);
            }
            uint32_t ah[2][4], al[2][4];
            {
                uint32_t ra = sbase + (warp_m * 64 + ar) * 64
                            + (((k16 * 2 + a16) ^ sA) << 4);
                LDSM_X4(ah[0][0], ah[0][1], ah[0][2], ah[0][3], ra);
                LDSM_X4(al[0][0], al[0][1], al[0][2], al[0][3], ra + 8192);
            }
            #pragma unroll
            for (int i = 0; i < 4; i++) {
                const int cur = i & 1;
                if (i < 3) {
                    const int nxt = cur ^ 1;
                    uint32_t ra = sbase + (warp_m * 64 + (i + 1) * 16 + ar) * 64
                                + (((k16 * 2 + a16) ^ sA) << 4);
                    LDSM_X4(ah[nxt][0], ah[nxt][1], ah[nxt][2], ah[nxt][3], ra);
                    LDSM_X4(al[nxt][0], al[nxt][1], al[nxt][2], al[nxt][3], ra + 8192);
                }
                #pragma unroll
                for (int j = 0; j < 4; j++) {
                    mma_bf16(acc[i][j], ah[cur], bh[j]);
                    mma_bf16(acc[i][j], ah[cur], bl[j]);
                    mma_bf16(acc[i][j], al[cur], bh[j]);
                }
            }
        }
    }

    const int g = lane >> 2;
    const int t = lane & 3;
    #pragma unroll
    for (int i = 0; i < 4; i++) {
        int od0 = m0 + warp_m * 64 + i * 16 + g;
        float bv0 = bias[od0];
        float bv1 = bias[od0 + 8];
        #pragma unroll
        for (int j = 0; j < 4; j++) {
            int l = n0 + warp_n * 32 + j * 8 + t * 2;
            *(float2*)&C[(size_t)od0 * LSEQ + l] =
                make_float2(acc[i][j][0] + bv0, acc[i][j][1] + bv0);
            *(float2*)&C[(size_t)(od0 + 8) * LSEQ + l] =
                make_float2(acc[i][j][2] + bv1, acc[i][j][3] + bv1);
        }
    }
}

// ---------------------------------------------------------------------------
// gemm_out: out[b,l,e] = sum_d v[b,d,l]*w_out[e,d] + b_out[e]
#define GO_STAGE 32768
#define GO_SMEM  (3 * GO_STAGE)

__global__ __launch_bounds__(256, 2) void gemm_out_mma(const float* __restrict__ bias,
                                                       float* __restrict__ O)
{
    extern __shared__ char smem[];
    const uint32_t sb = smem_u32(smem);
    const int tid  = threadIdx.x;
    const int lane = tid & 31;
    const int wid  = tid >> 5;
    const int warp_m = wid >> 2;
    const int warp_n = wid & 3;

    const int b  = blockIdx.z;
    const int m0 = blockIdx.y * 128;   // l
    const int n0 = blockIdx.x * 128;   // e
    float* C = O + (size_t)b * LSEQ * DDIM;

    const int tile = tid >> 6;
    const int tloc = tid & 63;
    const char* gbase;
    if      (tile == 0) gbase = (const char*)g_vh + (size_t)(b * DDIM) * 8192 + (size_t)m0 * 2;
    else if (tile == 1) gbase = (const char*)g_vl + (size_t)(b * DDIM) * 8192 + (size_t)m0 * 2;
    else if (tile == 2) gbase = (const char*)g_oh + (size_t)n0 * 2048;
    else                gbase = (const char*)g_ol + (size_t)n0 * 2048;

    float acc[4][4][4];
    #pragma unroll
    for (int i = 0; i < 4; i++)
        #pragma unroll
        for (int j = 0; j < 4; j++)
            #pragma unroll
            for (int r = 0; r < 4; r++) acc[i][j][r] = 0.0f;

    const int tr  = (lane & 7) + ((lane & 16) ? 8 : 0);
    const int sT  = lane & 7;
    const int t16 = (lane & 8) ? 1 : 0;
    const int br  = lane & 7;
    const int sB  = (br >> 1) & 3;
    const int b16 = (lane & 8) ? 1 : 0;

    #pragma unroll
    for (int p = 0; p < 2; p++) {
        if (tile < 2) {
            #pragma unroll
            for (int o = 0; o < 8; o++) {
                int idx = tloc + o * 64, row = idx >> 4, c16 = idx & 15;
                uint32_t dst = sb + p * GO_STAGE + tile * 8192 + row * 256
                             + (((c16 ^ (row & 7))) << 4);
                CP_ASYNC16(dst, gbase + (size_t)(p * 32 + row) * 8192 + c16 * 16);
            }
        } else {
            #pragma unroll
            for (int o = 0; o < 8; o++) {
                int idx = tloc + o * 64, row = idx >> 2, c = idx & 3;
                uint32_t dst = sb + p * GO_STAGE + (tile - 2) * 8192 + 16384 + row * 64
                             + (((c ^ ((row >> 1) & 3))) << 4);
                CP_ASYNC16(dst, gbase + (size_t)row * 2048 + p * 64 + c * 16);
            }
        }
        CP_COMMIT();
    }

    for (int ch = 0; ch < 32; ch++) {
        CP_WAIT1();
        __syncthreads();
        if (ch + 2 < 32) {
            const int st = (ch + 2) % 3;
            if (tile < 2) {
                #pragma unroll
                for (int o = 0; o < 8; o++) {
                    int idx = tloc + o * 64, row = idx >> 4, c16 = idx & 15;
                    uint32_t dst = sb + st * GO_STAGE + tile * 8192 + row * 256
                                 + (((c16 ^ (row & 7))) << 4);
                    CP_ASYNC16(dst, gbase + (size_t)((ch + 2) * 32 + row) * 8192 + c16 * 16);
                }
            } else {
                #pragma unroll
                for (int o = 0; o < 8; o++) {
                    int idx = tloc + o * 64, row = idx >> 2, c = idx & 3;
                    uint32_t dst = sb + st * GO_STAGE + (tile - 2) * 8192 + 16384 + row * 64
                                 + (((c ^ ((row >> 1) & 3))) << 4);
                    CP_ASYNC16(dst, gbase + (size_t)row * 2048 + (ch + 2) * 64 + c * 16);
                }
            }
        }
        CP_COMMIT();

        const uint32_t sbase = sb + (ch % 3) * GO_STAGE;
        #pragma unroll
        for (int k16 = 0; k16 < 2; k16++) {
            uint32_t bh[4][2], bl[4][2];
            #pragma unroll
            for (int j = 0; j < 4; j++) {
                uint32_t rb = sbase + 16384 + (warp_n * 32 + j * 8 + br) * 64
                            + (((k16 * 2 + b16) ^ sB) << 4);
                LDSM_X2(bh[j][0], bh[j][1], rb);
                LDSM_X2(bl[j][0], bl[j][1], rb + 8192);
            }
            uint32_t ah[2][4], al[2][4];
            {
                int rowd = k16 * 16 + tr;
                uint32_t ra = sbase + rowd * 256 + (((warp_m * 8 + t16) ^ sT) << 4);
                LDSM_X4_T(ah[0][0], ah[0][1], ah[0][2], ah[0][3], ra);
                LDSM_X4_T(al[0][0], al[0][1], al[0][2], al[0][3], ra + 8192);
            }
            #pragma unroll
            for (int i = 0; i < 4; i++) {
                const int cur = i & 1;
                if (i < 3) {
                    const int nxt = cur ^ 1;
                    int rowd = k16 * 16 + tr;
                    uint32_t ra = sbase + rowd * 256
                                + (((warp_m * 8 + (i + 1) * 2 + t16) ^ sT) << 4);
                    LDSM_X4_T(ah[nxt][0], ah[nxt][1], ah[nxt][2], ah[nxt][3], ra);
                    LDSM_X4_T(al[nxt][0], al[nxt][1], al[nxt][2], al[nxt][3], ra + 8192);
                }
                #pragma unroll
                for (int j = 0; j < 4; j++) {
                    mma_bf16(acc[i][j], ah[cur], bh[j]);
                    mma_bf16(acc[i][j], ah[cur], bl[j]);
                    mma_bf16(acc[i][j], al[cur], bh[j]);
                }
            }
        }
    }

    const int g = lane >> 2;
    const int t = lane & 3;
    #pragma unroll
    for (int j = 0; j < 4; j++) {
        int e = n0 + warp_n * 32 + j * 8 + t * 2;
        float bb0 = bias[e];
        float bb1 = bias[e + 1];
        #pragma unroll
        for (int i = 0; i < 4; i++) {
            int l = m0 + warp_m * 64 + i * 16 + g;
            *(float2*)&C[(size_t)l * DDIM + e] =
                make_float2(acc[i][j][0] + bb0, acc[i][j][1] + bb1);
            *(float2*)&C[(size_t)(l + 8) * DDIM + e] =
                make_float2(acc[i][j][2] + bb0, acc[i][j][3] + bb1);
        }
    }
}

// ---------------------------------------------------------------------------
__device__ __forceinline__ float conv3_at(const float* __restrict__ r, int l,
                                          float w0, float w1, float w2, float cb) {
    float left  = (l > 0)        ? r[l - 1] : 0.0f;
    float right = (l < LSEQ - 1) ? r[l + 1] : 0.0f;
    return w0 * left + w1 * r[l] + w2 * right + cb;
}

__global__ __launch_bounds__(FFT_THREADS, 3) void fftconv_kernel(
    const float* __restrict__ cw, const float* __restrict__ cbv)
{
    extern __shared__ float sm[];
    float* SR = sm;
    float* SI = sm + SM_HALF;
    const int c = blockIdx.x;
    const int b = c >> 9;
    const int dpair = c & (NPAIR - 1);
    const int ch0 = 2 * dpair, ch1 = ch0 + 1;
    const float inv = 1.0f / (float)NF;

    {
        const float* r2a = g_res + ((size_t)(b * 3 + 2) * DDIM + ch0) * LSEQ;
        const float* r2b = g_res + ((size_t)(b * 3 + 2) * DDIM + ch1) * LSEQ;
        const int oa = 2 * DDIM + ch0, ob = 2 * DDIM + ch1;
        float w0a = cw[oa * 3], w1a = cw[oa * 3 + 1], w2a = cw[oa * 3 + 2], cba = cbv[oa];
        float w0b = cw[ob * 3], w1b = cw[ob * 3 + 1], w2b = cw[ob * 3 + 2], cbb = cbv[ob];
        for (int i = threadIdx.x; i < LSEQ; i += FFT_THREADS) {
            SR[PADI(i)] = conv3_at(r2a, i, w0a, w1a, w2a, cba);
            SI[PADI(i)] = conv3_at(r2b, i, w0b, w1b, w2b, cbb);
        }
    }
    __syncthreads();

    #pragma unroll 1
    for (int n = 0; n < 2; n++) {
        fft_fwd_zp(SR, SI);

        const float2* Ap = g_A + ((size_t)n * NPAIR + dpair) * NK;
        const float2* Bp = g_B + ((size_t)n * NPAIR + dpair) * NK;
        for (int k = threadIdx.x; k <= LSEQ; k += FFT_THREADS) {
            int p = freq_to_slot(k);
            int q = freq_to_slot((NF - k) & (NF - 1));
            int ip = PADI(p), iq = PADI(q);
            float zr = SR[ip], zi = SI[ip];
            float wr = SR[iq], wi = SI[iq];
            float2 a  = Ap[k];
            float2 bb = Bp[k];
            float ypr = a.x * zr - a.y * zi + bb.x * wr + bb.y * wi;
            float ypi = a.x * zi + a.y * zr + bb.y * wr - bb.x * wi;
            SR[ip] = ypr; SI[ip] = ypi;
            if (q != p) {
                float yqr = a.x * wr + a.y * wi + bb.x * zr - bb.y * zi;
                float yqi = a.x * wi - a.y * wr - bb.x * zi - bb.y * zr;
                SR[iq] = yqr; SI[iq] = yqi;
            }
        }
        __syncthreads();

        fft_inv_half(SR, SI);

        const float* rna = g_res + ((size_t)(b * 3 + n) * DDIM + ch0) * LSEQ;
        const float* rnb = g_res + ((size_t)(b * 3 + n) * DDIM + ch1) * LSEQ;
        const int oa = n * DDIM + ch0, ob = n * DDIM + ch1;
        float w0a = cw[oa * 3], w1a = cw[oa * 3 + 1], w2a = cw[oa * 3 + 2], cba = cbv[oa];
        float w0b = cw[ob * 3], w1b = cw[ob * 3 + 1], w2b = cw[ob * 3 + 2], cbb = cbv[ob];

        if (n == 0) {
            for (int l = threadIdx.x; l < LSEQ; l += FFT_THREADS) {
                int ip = PADI(l);
                SR[ip] = SR[ip] * inv * conv3_at(rna, l, w0a, w1a, w2a, cba);
                SI[ip] = SI[ip] * inv * conv3_at(rnb, l, w0b, w1b, w2b, cbb);
            }
            __syncthreads();
        } else {
            uint32_t* vh0 = g_vh + ((size_t)(b * DDIM + ch0)) * (LSEQ / 2);
            uint32_t* vl0 = g_vl + ((size_t)(b * DDIM + ch0)) * (LSEQ / 2);
            uint32_t* vh1 = g_vh + ((size_t)(b * DDIM + ch1)) * (LSEQ / 2);
            uint32_t* vl1 = g_vl + ((size_t)(b * DDIM + ch1)) * (LSEQ / 2);
            for (int l2 = threadIdx.x; l2 < LSEQ / 2; l2 += FFT_THREADS) {
                int l = 2 * l2;
                float y0a = SR[PADI(l)]     * inv * conv3_at(rna, l,     w0a, w1a, w2a, cba);
                float y0b = SR[PADI(l + 1)] * inv * conv3_at(rna, l + 1, w0a, w1a, w2a, cba);
                float y1a = SI[PADI(l)]     * inv * conv3_at(rnb, l,     w0b, w1b, w2b, cbb);
                float y1b = SI[PADI(l + 1)] * inv * conv3_at(rnb, l + 1, w0b, w1b, w2b, cbb);
                vh0[l2] = pack_hi(y0a, y0b); vl0[l2] = pack_lo(y0a, y0b);
                vh1[l2] = pack_hi(y1a, y1b); vl1[l2] = pack_lo(y1a, y1b);
            }
        }
    }
}

// ---------------------------------------------------------------------------
extern "C" void kernel_launch(void* const* d_in, const int* in_sizes, int n_in,
                              void* d_out, int out_size)
{
    const float* u          = (const float*)d_in[0];
    const float* w_in       = (const float*)d_in[1];
    const float* b_in       = (const float*)d_in[2];
    const float* conv_w     = (const float*)d_in[3];
    const float* conv_b     = (const float*)d_in[4];
    const float* w1         = (const float*)d_in[5];
    const float* b1         = (const float*)d_in[6];
    const float* w2         = (const float*)d_in[7];
    const float* b2         = (const float*)d_in[8];
    const float* filt_bias  = (const float*)d_in[9];
    const float* filt_decay = (const float*)d_in[10];
    const float* w_out      = (const float*)d_in[11];
    const float* b_out      = (const float*)d_in[12];
    float* out = (float*)d_out;

    static bool attr_set = false;
    if (!attr_set) {
        cudaFuncSetAttribute(fftconv_kernel, cudaFuncAttributeMaxDynamicSharedMemorySize, FFT_SMEM);
        cudaFuncSetAttribute(gemm_in_mma,    cudaFuncAttributeMaxDynamicSharedMemorySize, GI_SMEM);
        cudaFuncSetAttribute(gemm_out_mma,   cudaFuncAttributeMaxDynamicSharedMemorySize, GO_SMEM);
        cudaFuncSetAttribute(filter_gemm,    cudaFuncAttributeMaxDynamicSharedMemorySize, 65536);
        attr_set = true;
    }

    // 1: prep — conversions + twiddles + sact
    prep_kernel<<<PREP_GRID, 256>>>(w_in, u, w_out, w1, b1);
    // 2: filter GEMM (produces g_h)
    filter_gemm<<<512, 256, 65536>>>(w2, b2, filt_bias, filt_decay);
    // 3: hfft (1024 CTAs) fused with gemm_in (1536 CTAs)
    gemm_in_mma<<<2 * NPAIR + 1536, 256, GI_SMEM>>>(b_in);
    // 4: fftconv (profiled slot, 3 CTAs/SM)
    fftconv_kernel<<<BSZ * NPAIR, FFT_THREADS, FFT_SMEM>>>(conv_w, conv_b);
    // 5: output GEMM
    gemm_out_mma<<<dim3(DDIM / 128, LSEQ / 128, BSZ), 256, GO_SMEM>>>(b_out, out);
}